// round 7
// baseline (speedup 1.0000x reference)
#include <cuda_runtime.h>
#include <math.h>

// Problem constants
static constexpr int NB = 8, NC = 256, NH = 128, NW = 128;
static constexpr int HW = NH * NW;
static constexpr float EPSF = 1e-8f;

typedef unsigned long long ull;

// Device scratch (atomically accumulated; reset by the finalizing block)
__device__ float g_total[NB];
__device__ int   g_cnt[NB];
__device__ int   g_inc[NB];
__device__ int   g_arrive;

__device__ __forceinline__ ull pk(float lo, float hi) {
    ull r;
    asm("mov.b64 %0, {%1, %2};" : "=l"(r) : "f"(lo), "f"(hi));
    return r;
}
__device__ __forceinline__ void upk(ull v, float& lo, float& hi) {
    asm("mov.b64 {%0, %1}, %2;" : "=f"(lo), "=f"(hi) : "l"(v));
}
__device__ __forceinline__ void fma2(ull& a, ull x, ull y) {
    asm("fma.rn.f32x2 %0, %1, %2, %0;" : "+l"(a) : "l"(x), "l"(y));
}
__device__ __forceinline__ float2 nrm2(ull s) {
    float lo, hi; upk(s, lo, hi);
    return make_float2(fmaxf(sqrtf(lo), EPSF), fmaxf(sqrtf(hi), EPSF));
}

// Register window: 16 floats (rows y, y+1, y+2), named members only
struct Win { float2 P0, P2, Q0, Q2, Q4, R0, R2, R4; };

// ---------------------------------------------------------------------------
// Fully fused kernel. Tile = 8 rows x 32 cols. 128 threads, 2 px/thread
// (px pair along x). All 256 channels per block -> complete dots + norms ->
// inline epilogue. Grid = (4, 16, 8) = 512 blocks (single resident wave).
// ---------------------------------------------------------------------------
__global__ __launch_bounds__(128, 4) void fused_kernel(
    const float* __restrict__ er,
    const int*   __restrict__ seg,
    const int*   __restrict__ gtb,
    float*       __restrict__ out)
{
    __shared__ float shN[10 * 36];
    __shared__ int   shL[10 * 36];
    __shared__ float sRf[4];
    __shared__ int   sRc[4], sRi[4], sLast;

    const int tilex = blockIdx.x, tiley = blockIdx.y, b = blockIdx.z;
    const int tid = threadIdx.x;
    const int r = tid >> 4;          // 0..7 (core row within tile)
    const int x = tid & 15;          // 0..15 (x pair index)
    const int h0 = tiley * 8, w0 = tilex * 32;
    const int gy = h0 + r;
    const int gx0 = w0 + 2 * x;
    const bool isR7 = (r == 7), isX0 = (x == 0), isX15 = (x == 15);

    // ---- stage labels: rows [h0, h0+10), cols [w0-2, w0+34) ----
    const int* segb = seg + b * HW;
    const int* gtbb = gtb + b * HW;
    for (int i = tid; i < 360; i += 128) {
        int rr = i / 36, cc = i - rr * 36;
        int gh = h0 + rr, gw = w0 - 2 + cc;
        int code = 0x7FFF;                 // OOB: never matches, flags 0
        if (gh < NH && gw >= 0 && gw < NW) {
            int s = segb[gh * NW + gw], g = gtbb[gh * NW + gw];
            int s0 = (s == 255) ? 0 : s;
            int g0 = (g == 255) ? 0 : g;
            bool fg    = (s0 * g0 > 0);
            bool inter = (gh >= 2 && gh < NH - 2 && gw >= 2 && gw < NW - 2);
            code = (s & 0xFFFF) | ((fg && inter) ? 0x10000 : 0) | (fg ? 0x20000 : 0);
        }
        shL[i] = code;
    }
    if (tid == 0) { shN[0] = 1.f; shN[1] = 1.f; }   // row 0 left halo: never used

    // ---- load offsets (upper clamps keep 8B alignment; garbage is weight-0) ----
    const int oP  = gy * NW + gx0;
    const int oP2 = min(oP + 2,          HW - 2);
    const int oQ0 = min(oP + NW - 2,     HW - 2);
    const int oQ2 = min(oP + NW,         HW - 2);
    const int oQ4 = min(oP + NW + 2,     HW - 2);
    const int oR0 = min(oP + 2 * NW - 2, HW - 2);
    const int oR2 = min(oP + 2 * NW,     HW - 2);
    const int oR4 = min(oP + 2 * NW + 2, HW - 2);
    const float* plane = er + (size_t)b * NC * HW;

#define LOADW(W, C) {                                                     \
        const float* _p = plane + (size_t)(C) * HW;                       \
        (W).P0 = *(const float2*)(_p + oP);                               \
        (W).P2 = *(const float2*)(_p + oP2);                              \
        (W).Q0 = *(const float2*)(_p + oQ0);                              \
        (W).Q2 = *(const float2*)(_p + oQ2);                              \
        (W).Q4 = *(const float2*)(_p + oQ4);                              \
        (W).R0 = *(const float2*)(_p + oR0);                              \
        (W).R2 = *(const float2*)(_p + oR2);                              \
        (W).R4 = *(const float2*)(_p + oR4);                              \
    }

    ull a[12];
#pragma unroll
    for (int d = 0; d < 12; d++) a[d] = 0ull;
    ull selfP = 0, selfPR = 0, selfQL = 0, selfQ8 = 0, selfQR = 0;
    ull selfRL = 0, selfR9 = 0, selfRR = 0;

#define COMPUTE(W) {                                                      \
        const float p0 = (W).P0.x, p1 = (W).P0.y;                         \
        const float p2 = (W).P2.x, p3 = (W).P2.y;                         \
        const float q0 = (W).Q0.x, q1 = (W).Q0.y, q2 = (W).Q2.x;          \
        const float q3 = (W).Q2.y, q4 = (W).Q4.x, q5 = (W).Q4.y;          \
        const float r0 = (W).R0.x, r1 = (W).R0.y, r2 = (W).R2.x;          \
        const float r3 = (W).R2.y, r4 = (W).R4.x, r5 = (W).R4.y;          \
        ull PP = pk(p0, p1);                                              \
        fma2(selfP, PP, PP);                                              \
        fma2(a[0], PP, pk(p1, p2));                                       \
        fma2(a[1], PP, pk(p2, p3));                                       \
        ull t;                                                            \
        t = pk(q0, q1); fma2(a[2], PP, t); if (isX0) fma2(selfQL, t, t);  \
        fma2(a[3], PP, pk(q1, q2));                                       \
        t = pk(q2, q3); fma2(a[4], PP, t); if (isR7) fma2(selfQ8, t, t);  \
        fma2(a[5], PP, pk(q3, q4));                                       \
        t = pk(q4, q5); fma2(a[6], PP, t);                                \
        if (isR7 && isX15) fma2(selfQR, t, t);                            \
        t = pk(r0, r1); fma2(a[7], PP, t);                                \
        if (isR7 && isX0) fma2(selfRL, t, t);                             \
        fma2(a[8], PP, pk(r1, r2));                                       \
        t = pk(r2, r3); fma2(a[9], PP, t); if (isR7) fma2(selfR9, t, t);  \
        fma2(a[10], PP, pk(r3, r4));                                      \
        t = pk(r4, r5); fma2(a[11], PP, t);                               \
        if (isR7 && isX15) fma2(selfRR, t, t);                            \
        if (isX15) { ull pr = pk(p2, p3); fma2(selfPR, pr, pr); }         \
    }

    Win wA, wB;
    LOADW(wA, 0);
    LOADW(wB, 1);
#pragma unroll 1
    for (int c = 0; c < NC; c += 2) {
        COMPUTE(wA);
        if (c + 2 < NC) LOADW(wA, c + 2);
        COMPUTE(wB);
        if (c + 3 < NC) LOADW(wB, c + 3);
    }
#undef LOADW
#undef COMPUTE

    // ---- norms into SMEM (designated writers cover the whole 10x36 halo) ----
    {
        float2 n = nrm2(selfP);
        shN[r * 36 + 2 + 2 * x] = n.x;
        shN[r * 36 + 3 + 2 * x] = n.y;
        if (isX15) { float2 m = nrm2(selfPR); shN[r * 36 + 34] = m.x; shN[r * 36 + 35] = m.y; }
        if (isX0)  { float2 m = nrm2(selfQL); shN[(r + 1) * 36 + 0] = m.x; shN[(r + 1) * 36 + 1] = m.y; }
        if (isR7) {
            float2 m8 = nrm2(selfQ8); shN[8 * 36 + 2 + 2 * x] = m8.x; shN[8 * 36 + 3 + 2 * x] = m8.y;
            float2 m9 = nrm2(selfR9); shN[9 * 36 + 2 + 2 * x] = m9.x; shN[9 * 36 + 3 + 2 * x] = m9.y;
            if (isX0)  { float2 m = nrm2(selfRL); shN[9 * 36 + 0] = m.x; shN[9 * 36 + 1] = m.y; }
            if (isX15) {
                float2 mA = nrm2(selfQR); shN[8 * 36 + 34] = mA.x; shN[8 * 36 + 35] = mA.y;
                float2 mB = nrm2(selfRR); shN[9 * 36 + 34] = mB.x; shN[9 * 36 + 35] = mB.y;
            }
        }
    }
    __syncthreads();

    // ---- epilogue: 2 core px per thread ----
    const int dof[12] = {1, 2, 34, 35, 36, 37, 38, 70, 71, 72, 73, 74};
    float dlo[12], dhi[12];
#pragma unroll
    for (int d = 0; d < 12; d++) upk(a[d], dlo[d], dhi[d]);

    float acc = 0.f;
    int cnt = 0, inc = 0;
#define EPI(J, DARR) {                                                    \
        int mp = r * 36 + 2 + 2 * x + (J);                                \
        int pcode = shL[mp];                                              \
        float vp = (float)((pcode >> 16) & 1);                            \
        cnt += (pcode >> 16) & 1;                                         \
        inc |= (pcode >> 17) & 1;                                         \
        int sp = pcode & 0xFFFF;                                          \
        float np = shN[mp];                                               \
        _Pragma("unroll")                                                 \
        for (int d = 0; d < 12; d++) {                                    \
            int ncode = shL[mp + dof[d]];                                 \
            float vn = (float)((ncode >> 16) & 1);                        \
            float wgt = vp + vn;                                          \
            float nn = shN[mp + dof[d]];                                  \
            float cosv = DARR[d] / (np * nn);                             \
            int sn = ncode & 0xFFFF;                                      \
            float lab = (sp == sn && sp < 2) ? 1.f : 0.f;                 \
            float diff = cosv - lab;                                      \
            acc += wgt * diff * diff;                                     \
        }                                                                 \
    }
    EPI(0, dlo);
    EPI(1, dhi);
#undef EPI

    // ---- block reduce (4 warps) + atomic merge per image ----
    unsigned mask = 0xFFFFFFFFu;
#pragma unroll
    for (int off = 16; off > 0; off >>= 1) {
        acc += __shfl_down_sync(mask, acc, off);
        cnt += __shfl_down_sync(mask, cnt, off);
        inc |= __shfl_down_sync(mask, inc, off);
    }
    if ((tid & 31) == 0) { sRf[tid >> 5] = acc; sRc[tid >> 5] = cnt; sRi[tid >> 5] = inc; }
    __syncthreads();
    if (tid == 0) {
        float a4 = sRf[0] + sRf[1] + sRf[2] + sRf[3];
        int   c4 = sRc[0] + sRc[1] + sRc[2] + sRc[3];
        int   i4 = sRi[0] | sRi[1] | sRi[2] | sRi[3];
        atomicAdd(&g_total[b], a4);
        if (c4) atomicAdd(&g_cnt[b], c4);
        if (i4) atomicOr(&g_inc[b], 1);
        __threadfence();
        int t = atomicAdd(&g_arrive, 1);
        sLast = (t == 4 * 16 * NB - 1) ? 1 : 0;
    }
    __syncthreads();

    // ---- fused finalize: last block computes the scalar loss + resets state ----
    if (sLast && tid < 32) {
        float li = 0.f;
        int sn = 0;
        if (tid < NB) {
            float tot = g_total[tid];
            int c2 = g_cnt[tid], i2 = g_inc[tid];
            g_total[tid] = 0.f; g_cnt[tid] = 0; g_inc[tid] = 0;   // reset for replay
            li = i2 ? (tot / fmaxf((float)c2, 1.f) / 24.f) : 0.f;
            sn = i2 ? 1 : 0;
        }
#pragma unroll
        for (int off = 16; off > 0; off >>= 1) {
            li += __shfl_down_sync(mask, li, off);
            sn += __shfl_down_sync(mask, sn, off);
        }
        if (tid == 0) {
            out[0] = li / (float)(sn > 0 ? sn : 1);
            g_arrive = 0;   // reset for next graph replay
        }
    }
}

extern "C" void kernel_launch(void* const* d_in, const int* in_sizes, int n_in,
                              void* d_out, int out_size) {
    const float* er  = (const float*)d_in[0];
    const int*   seg = (const int*)d_in[1];
    const int*   gtb = (const int*)d_in[2];

    dim3 grid(NW / 32, NH / 8, NB);   // 4 x 16 x 8 = 512 blocks
    fused_kernel<<<grid, 128>>>(er, seg, gtb, (float*)d_out);
}

// round 9
// speedup vs baseline: 1.6008x; 1.6008x over previous
#include <cuda_runtime.h>
#include <math.h>

// Problem constants
static constexpr int NB = 8, NC = 256, NH = 128, NW = 128;
static constexpr int HW = NH * NW;
static constexpr float EPSF = 1e-8f;

static constexpr int CSPLIT = 4;           // channel slices
static constexpr int CPG = NC / CSPLIT;    // 64 channels per block
static constexpr int CC = 8;               // channels per staged chunk
static constexpr int NCHUNK = CPG / CC;    // 8
static constexpr int SROW = 40;            // smem floats per halo row (16B-aligned)
static constexpr int SPLANE = 18 * SROW;   // 720 floats per channel plane
static constexpr int NSTRIP = 64;          // epilogue: 2-row strips

typedef unsigned long long ull;
typedef unsigned int u32;

// Device scratch (dense writes only)
__device__ float g_dots[CSPLIT][(size_t)NB * HW * 12];
__device__ float g_nsq [CSPLIT][NB * HW];
__device__ float g_stotal[NB * NSTRIP];
__device__ int   g_scnt [NB * NSTRIP];
__device__ int   g_sinc [NB * NSTRIP];
__device__ int   g_arrive;                 // zero-init; reset by last block

__device__ __forceinline__ ull pk(float lo, float hi) {
    ull r;
    asm("mov.b64 %0, {%1, %2};" : "=l"(r) : "f"(lo), "f"(hi));
    return r;
}
__device__ __forceinline__ ull u2(float2 v) { return pk(v.x, v.y); }
__device__ __forceinline__ void upk(ull v, float& lo, float& hi) {
    asm("mov.b64 {%0, %1}, %2;" : "=f"(lo), "=f"(hi) : "l"(v));
}
__device__ __forceinline__ void fma2(ull& a, ull x, ull y) {
    asm("fma.rn.f32x2 %0, %1, %2, %0;" : "+l"(a) : "l"(x), "l"(y));
}

// ---------------------------------------------------------------------------
// Kernel 1: partial dots + norm^2. cp.async double-buffered channel-plane SMEM.
// Tile 16x32 core (halo 18x[-4,36)), 128 threads = 2x2 px quads.
// Grid (4, 8, NB*CSPLIT) = 1024 blocks.
// ---------------------------------------------------------------------------
__global__ __launch_bounds__(128, 4) void partial_kernel(const float* __restrict__ er)
{
    __shared__ float sbuf[2][CC * SPLANE];   // 2 x 23040 B

    const int b  = blockIdx.z >> 2;
    const int cs = blockIdx.z & 3;
    const int h0 = blockIdx.y * 16;
    const int w0 = blockIdx.x * 32;
    const int tid = threadIdx.x;
    const int qx = tid & 15;
    const int qy = tid >> 4;

    const float* erblk = er + ((size_t)b * NC + cs * CPG) * HW;

    // ---- precompute staging slots: 1440 cp.async ops = 8ch x 18row x 10grp ----
    int relg[12];   // >=0: plane-relative src offset; <0: zero-fill
    int rels[12];   // >=0: smem byte offset; <0: skip entirely
#pragma unroll
    for (int k = 0; k < 12; k++) {
        int op = tid + k * 128;
        if (op < 1440) {
            int ch  = op / 180;
            int rem = op - ch * 180;
            int row = rem / 10;
            int grp = rem - row * 10;
            int gflat = (h0 + row) * NW + (w0 - 4) + grp * 4;
            bool v = (gflat >= 0) && (gflat <= HW - 4);
            relg[k] = v ? (ch * HW + gflat) : -1;
            rels[k] = (ch * SPLANE + row * SROW + grp * 4) * 4;
        } else {
            relg[k] = -1;
            rels[k] = -1;
        }
    }

    u32 sb0 = (u32)__cvta_generic_to_shared(&sbuf[0][0]);
    u32 sb1 = (u32)__cvta_generic_to_shared(&sbuf[1][0]);

#define ISSUE(CH, SB) {                                                        \
        const float* gb = erblk + (size_t)(CH) * CC * HW;                      \
        _Pragma("unroll")                                                      \
        for (int k = 0; k < 12; k++) {                                         \
            if (rels[k] >= 0) {                                                \
                int rg = relg[k];                                              \
                int sz = (rg >= 0) ? 16 : 0;                                   \
                const float* src = gb + ((rg >= 0) ? rg : 0);                  \
                asm volatile("cp.async.cg.shared.global [%0], [%1], 16, %2;"   \
                             :: "r"((SB) + rels[k]), "l"(src), "r"(sz)         \
                             : "memory");                                      \
            }                                                                  \
        }                                                                      \
        asm volatile("cp.async.commit_group;" ::: "memory");                   \
    }

    ull a0[12], a1[12];
#pragma unroll
    for (int d = 0; d < 12; d++) { a0[d] = 0ull; a1[d] = 0ull; }
    ull selfA = 0ull, selfB = 0ull;

    // f-row pointer: pixel rows 2qy..2qy+3, first core col 2qx (halo col 2qx+4)
    const int tboff = (2 * qy) * SROW + (2 * qx + 4);

#define COMPUTE(BUF) {                                                         \
        const float* tb = (BUF) + tboff;                                       \
        _Pragma("unroll")                                                      \
        for (int ch = 0; ch < CC; ch++) {                                      \
            const float* pl = tb + ch * SPLANE;                                \
            float2 F0 = *(const float2*)(pl);                                  \
            float2 F2 = *(const float2*)(pl + 2);                              \
            float2 Gm = *(const float2*)(pl + SROW - 2);                       \
            float2 G0 = *(const float2*)(pl + SROW);                           \
            float2 G2 = *(const float2*)(pl + SROW + 2);                       \
            float2 Hm = *(const float2*)(pl + 2 * SROW - 2);                   \
            float2 H0 = *(const float2*)(pl + 2 * SROW);                       \
            float2 H2 = *(const float2*)(pl + 2 * SROW + 2);                   \
            float2 Km = *(const float2*)(pl + 3 * SROW - 2);                   \
            float2 K0 = *(const float2*)(pl + 3 * SROW);                       \
            float2 K2 = *(const float2*)(pl + 3 * SROW + 2);                   \
            ull PP = u2(F0), QQ = u2(G0);                                      \
            ull pF  = pk(F0.y, F2.x);                                          \
            ull pG1 = pk(Gm.y, G0.x), pG2 = pk(G0.y, G2.x);                    \
            ull pH1 = pk(Hm.y, H0.x), pH2 = pk(H0.y, H2.x);                    \
            ull pK1 = pk(Km.y, K0.x), pK2 = pk(K0.y, K2.x);                    \
            ull uF2 = u2(F2), uGm = u2(Gm), uG2 = u2(G2);                      \
            ull uHm = u2(Hm), uH0 = u2(H0), uH2 = u2(H2);                      \
            ull uKm = u2(Km), uK0 = u2(K0), uK2 = u2(K2);                      \
            fma2(selfA, PP, PP);  fma2(selfB, QQ, QQ);                         \
            fma2(a0[0], PP, pF);  fma2(a0[1], PP, uF2);                        \
            fma2(a0[2], PP, uGm); fma2(a0[3], PP, pG1); fma2(a0[4], PP, QQ);   \
            fma2(a0[5], PP, pG2); fma2(a0[6], PP, uG2);                        \
            fma2(a0[7], PP, uHm); fma2(a0[8], PP, pH1); fma2(a0[9], PP, uH0);  \
            fma2(a0[10], PP, pH2); fma2(a0[11], PP, uH2);                      \
            fma2(a1[0], QQ, pG2); fma2(a1[1], QQ, uG2);                        \
            fma2(a1[2], QQ, uHm); fma2(a1[3], QQ, pH1); fma2(a1[4], QQ, uH0);  \
            fma2(a1[5], QQ, pH2); fma2(a1[6], QQ, uH2);                        \
            fma2(a1[7], QQ, uKm); fma2(a1[8], QQ, pK1); fma2(a1[9], QQ, uK0);  \
            fma2(a1[10], QQ, pK2); fma2(a1[11], QQ, uK2);                      \
        }                                                                      \
    }

    // ---- pipeline: prolog loads 2 chunks, then compute/prefetch overlap ----
    ISSUE(0, sb0);
    ISSUE(1, sb1);
#pragma unroll 1
    for (int c = 0; c < NCHUNK; c++) {
        if (c < NCHUNK - 1)
            asm volatile("cp.async.wait_group 1;" ::: "memory");
        else
            asm volatile("cp.async.wait_group 0;" ::: "memory");
        __syncthreads();
        const float* bp = (c & 1) ? &sbuf[1][0] : &sbuf[0][0];
        COMPUTE(bp);
        __syncthreads();
        if (c + 2 < NCHUNK) {
            u32 sb = (c & 1) ? sb1 : sb0;
            ISSUE(c + 2, sb);
        }
    }
#undef ISSUE
#undef COMPUTE

    // ---- writeback (dense; each element written exactly once) ----
    const int p00 = (h0 + 2 * qy) * NW + (w0 + 2 * qx);
    float* dbase = g_dots[cs] + (size_t)b * HW * 12;
    float v0[12], v1[12], v2[12], v3[12];
#pragma unroll
    for (int d = 0; d < 12; d++) {
        upk(a0[d], v0[d], v1[d]);
        upk(a1[d], v2[d], v3[d]);
    }
#define ST12(P, V) {                                                           \
        float4* dst = (float4*)(dbase + (size_t)(P) * 12);                     \
        dst[0] = make_float4(V[0], V[1], V[2],  V[3]);                         \
        dst[1] = make_float4(V[4], V[5], V[6],  V[7]);                         \
        dst[2] = make_float4(V[8], V[9], V[10], V[11]);                        \
    }
    ST12(p00,          v0);
    ST12(p00 + 1,      v1);
    ST12(p00 + NW,     v2);
    ST12(p00 + NW + 1, v3);
#undef ST12
    float s0, s1, s2, s3;
    upk(selfA, s0, s1);
    upk(selfB, s2, s3);
    float* nptr = g_nsq[cs] + b * HW;
    *(float2*)(nptr + p00)      = make_float2(s0, s1);
    *(float2*)(nptr + p00 + NW) = make_float2(s2, s3);
}

// ---------------------------------------------------------------------------
// Kernel 2: epilogue + fused finalize. Block = (2-row strip, image), 256 thr.
// ---------------------------------------------------------------------------
__global__ __launch_bounds__(256) void epilogue_kernel(
    const int* __restrict__ seg, const int* __restrict__ gtb,
    float* __restrict__ out)
{
    __shared__ float shN[6 * 132];
    __shared__ int   shL[6 * 132];
    __shared__ float sRf[8];
    __shared__ int   sRc[8], sRi[8], sLast;

    const int strip = blockIdx.x;
    const int b     = blockIdx.y;
    const int h0    = strip * 2;
    const int tid   = threadIdx.x;
    const int* segb = seg + b * HW;
    const int* gtbb = gtb + b * HW;

    // Stage norms + label codes for rows [h0-2, h0+4), cols [-2, 130)
    for (int i = tid; i < 6 * 132; i += 256) {
        int r = i / 132, c = i - r * 132;
        int gh = h0 - 2 + r, gw = c - 2;
        float nrm = 1.f;
        int code = 0x7FFF;
        if (gh >= 0 && gh < NH && gw >= 0 && gw < NW) {
            int idx = b * HW + gh * NW + gw;
            float ns = g_nsq[0][idx] + g_nsq[1][idx] + g_nsq[2][idx] + g_nsq[3][idx];
            nrm = fmaxf(sqrtf(ns), EPSF);
            int li = gh * NW + gw;
            int s = segb[li], g = gtbb[li];
            int s0 = (s == 255) ? 0 : s;
            int g0 = (g == 255) ? 0 : g;
            bool fg    = (s0 * g0 > 0);
            bool inter = (gh >= 2 && gh < NH - 2 && gw >= 2 && gw < NW - 2);
            code = (s & 0xFFFF) | ((fg && inter) ? 0x10000 : 0) | (fg ? 0x20000 : 0);
        }
        shN[i] = nrm;
        shL[i] = code;
    }
    __syncthreads();

    const int ty = tid >> 7, tx = tid & 127;
    const int p  = (h0 + ty) * NW + tx;

    // Sum the 4 slice dot-partials
    float dsum[12];
    {
        const size_t off = ((size_t)b * HW + p) * 12;
        float4 a0, a1, a2;
        {
            const float4* s = (const float4*)(g_dots[0] + off);
            a0 = s[0]; a1 = s[1]; a2 = s[2];
        }
#pragma unroll
        for (int cs = 1; cs < CSPLIT; cs++) {
            const float4* s = (const float4*)(g_dots[cs] + off);
            float4 t0 = s[0], t1 = s[1], t2 = s[2];
            a0.x += t0.x; a0.y += t0.y; a0.z += t0.z; a0.w += t0.w;
            a1.x += t1.x; a1.y += t1.y; a1.z += t1.z; a1.w += t1.w;
            a2.x += t2.x; a2.y += t2.y; a2.z += t2.z; a2.w += t2.w;
        }
        dsum[0] = a0.x; dsum[1] = a0.y; dsum[2]  = a0.z; dsum[3]  = a0.w;
        dsum[4] = a1.x; dsum[5] = a1.y; dsum[6]  = a1.z; dsum[7]  = a1.w;
        dsum[8] = a2.x; dsum[9] = a2.y; dsum[10] = a2.z; dsum[11] = a2.w;
    }

    const int mp = (ty + 2) * 132 + (tx + 2);
    const int dof[12] = {1, 2,
                         132 - 2, 132 - 1, 132, 132 + 1, 132 + 2,
                         264 - 2, 264 - 1, 264, 264 + 1, 264 + 2};

    int pcode = shL[mp];
    float vp  = (float)((pcode >> 16) & 1);
    int   cnt = (pcode >> 16) & 1;
    int   inc = (pcode >> 17) & 1;
    int   sp  = pcode & 0xFFFF;
    float np  = shN[mp];

    float acc = 0.f;
#pragma unroll
    for (int d = 0; d < 12; d++) {
        int ncode = shL[mp + dof[d]];
        float vn  = (float)((ncode >> 16) & 1);
        float wgt = vp + vn;
        float nn  = shN[mp + dof[d]];
        float cosv = dsum[d] / (np * nn);
        int sn = ncode & 0xFFFF;
        float lab = (sp == sn && sp < 2) ? 1.f : 0.f;
        float diff = cosv - lab;
        acc += wgt * diff * diff;
    }

    // Block reduce (8 warps)
    unsigned mask = 0xFFFFFFFFu;
#pragma unroll
    for (int off = 16; off > 0; off >>= 1) {
        acc += __shfl_down_sync(mask, acc, off);
        cnt += __shfl_down_sync(mask, cnt, off);
        inc |= __shfl_down_sync(mask, inc, off);
    }
    if ((tid & 31) == 0) { sRf[tid >> 5] = acc; sRc[tid >> 5] = cnt; sRi[tid >> 5] = inc; }
    __syncthreads();
    if (tid < 32) {
        float a = (tid < 8) ? sRf[tid] : 0.f;
        int   c = (tid < 8) ? sRc[tid] : 0;
        int   i = (tid < 8) ? sRi[tid] : 0;
#pragma unroll
        for (int off = 4; off > 0; off >>= 1) {
            a += __shfl_down_sync(mask, a, off);
            c += __shfl_down_sync(mask, c, off);
            i |= __shfl_down_sync(mask, i, off);
        }
        if (tid == 0) {
            g_stotal[b * NSTRIP + strip] = a;
            g_scnt [b * NSTRIP + strip] = c;
            g_sinc [b * NSTRIP + strip] = i;
            __threadfence();
            int t = atomicAdd(&g_arrive, 1);
            sLast = (t == NSTRIP * NB - 1) ? 1 : 0;
        }
    }
    __syncthreads();

    // Fused finalize: last block computes the scalar loss.
    if (sLast && tid < NB) {
        float tot = 0.f; int c = 0, i = 0;
        for (int s = 0; s < NSTRIP; s++) {
            tot += g_stotal[tid * NSTRIP + s];
            c   += g_scnt [tid * NSTRIP + s];
            i   |= g_sinc [tid * NSTRIP + s];
        }
        float li = i ? (tot / fmaxf((float)c, 1.f) / 24.f) : 0.f;
        unsigned m8 = 0xFFu;
        int sn = i ? 1 : 0;
#pragma unroll
        for (int off = 4; off > 0; off >>= 1) {
            li += __shfl_down_sync(m8, li, off);
            sn += __shfl_down_sync(m8, sn, off);
        }
        if (tid == 0) {
            out[0] = li / (float)(sn > 0 ? sn : 1);
            g_arrive = 0;   // reset for next graph replay
        }
    }
}

extern "C" void kernel_launch(void* const* d_in, const int* in_sizes, int n_in,
                              void* d_out, int out_size) {
    const float* er  = (const float*)d_in[0];
    const int*   seg = (const int*)d_in[1];
    const int*   gtb = (const int*)d_in[2];

    dim3 gridP(NW / 32, NH / 16, NB * CSPLIT);   // 4 x 8 x 32 = 1024 blocks
    partial_kernel<<<gridP, 128>>>(er);
    dim3 gridE(NSTRIP, NB);                      // 64 x 8 = 512 blocks
    epilogue_kernel<<<gridE, 256>>>(seg, gtb, (float*)d_out);
}